// round 2
// baseline (speedup 1.0000x reference)
#include <cuda_runtime.h>
#include <cuda_bf16.h>
#include <cstdint>

// GCN 2-layer, N=500000 nodes, E=16000000 edges.
//   deg_i = indeg(i) + 1 (self loop);  dis_i = rsqrt(deg_i)
//   s_i = dis_i * ( sum_{j->i} dis_j*x_j  +  dis_i*x_i )        (layer-1 scalar aggregate)
//   h_i[k] = relu(s_i*W1[k] + b1[k])                            (k = 0..7)
//   g_i[c] = sum_k h_i[k]*W2[k][c]                              (W2 applied BEFORE aggregation)
//   q_i = dis_i * g_i
//   out_i[c] = dis_i * ( sum_{j->i} q_j[c]  +  q_i[c] ) + b2[c]
//
// Edge-index dtype (int32 vs int64) is detected ON DEVICE: the reference asks
// for int64 but JAX without x64 silently produces int32. A probe kernel checks
// whether the first 64 values, read as int64, are all in [0, N); all edge
// kernels take a uniform branch on the resulting flag.

static constexpr int N_NODES = 500000;

__device__ int    g_is64;
__device__ float  g_deg[N_NODES];   // deg, then overwritten with dis
__device__ float  g_p[N_NODES];     // dis_j * x_j
__device__ float  g_t[N_NODES];     // scatter target layer 1
__device__ float2 g_q[N_NODES];     // dis_i * g_i
__device__ float2 g_U[N_NODES];     // scatter target layer 2

// ---------------------------------------------------------------- dtype probe
__global__ void k_detect(const long long* __restrict__ ei, int n_check, int N) {
    if (blockIdx.x == 0 && threadIdx.x == 0) {
        int ok = 1;
        for (int i = 0; i < n_check; i++) {
            long long v = ei[i];
            if (v < 0 || v >= (long long)N) { ok = 0; break; }
        }
        g_is64 = ok;
    }
}

// ---------------------------------------------------------------- init
__global__ void k_init(int n) {
    int i = blockIdx.x * blockDim.x + threadIdx.x;
    if (i < n) {
        g_deg[i] = 1.0f;              // self loop
        g_t[i]   = 0.0f;
        g_U[i]   = make_float2(0.0f, 0.0f);
    }
}

// ---------------------------------------------------------------- degree count (dst only)
__global__ void k_deg(const void* __restrict__ edge, int E) {
    long long base = (long long)(blockIdx.x * blockDim.x + threadIdx.x) * 4;
    if (g_is64) {
        const long long* dst = (const long long*)edge + E;
        if (base + 3 < E) {
            longlong2 d01 = *reinterpret_cast<const longlong2*>(dst + base);
            longlong2 d23 = *reinterpret_cast<const longlong2*>(dst + base + 2);
            atomicAdd(&g_deg[(int)d01.x], 1.0f);
            atomicAdd(&g_deg[(int)d01.y], 1.0f);
            atomicAdd(&g_deg[(int)d23.x], 1.0f);
            atomicAdd(&g_deg[(int)d23.y], 1.0f);
        } else {
            for (long long i = base; i < E; i++)
                atomicAdd(&g_deg[(int)dst[i]], 1.0f);
        }
    } else {
        const int* dst = (const int*)edge + E;
        if (base + 3 < E) {
            int4 d = *reinterpret_cast<const int4*>(dst + base);
            atomicAdd(&g_deg[d.x], 1.0f);
            atomicAdd(&g_deg[d.y], 1.0f);
            atomicAdd(&g_deg[d.z], 1.0f);
            atomicAdd(&g_deg[d.w], 1.0f);
        } else {
            for (long long i = base; i < E; i++)
                atomicAdd(&g_deg[dst[i]], 1.0f);
        }
    }
}

// ---------------------------------------------------------------- node pass A: dis, p
__global__ void k_nodeA(const float* __restrict__ x, int n) {
    int i = blockIdx.x * blockDim.x + threadIdx.x;
    if (i < n) {
        float dis = rsqrtf(g_deg[i]);
        g_deg[i] = dis;               // overwrite deg with dis
        g_p[i]   = dis * x[i];
    }
}

// ---------------------------------------------------------------- scatter 1 (scalar)
__global__ void k_scatter1(const void* __restrict__ edge, int E) {
    long long base = (long long)(blockIdx.x * blockDim.x + threadIdx.x) * 4;
    if (g_is64) {
        const long long* src = (const long long*)edge;
        const long long* dst = src + E;
        if (base + 3 < E) {
            longlong2 s01 = *reinterpret_cast<const longlong2*>(src + base);
            longlong2 s23 = *reinterpret_cast<const longlong2*>(src + base + 2);
            longlong2 d01 = *reinterpret_cast<const longlong2*>(dst + base);
            longlong2 d23 = *reinterpret_cast<const longlong2*>(dst + base + 2);
            float p0 = __ldg(&g_p[(int)s01.x]);
            float p1 = __ldg(&g_p[(int)s01.y]);
            float p2 = __ldg(&g_p[(int)s23.x]);
            float p3 = __ldg(&g_p[(int)s23.y]);
            atomicAdd(&g_t[(int)d01.x], p0);
            atomicAdd(&g_t[(int)d01.y], p1);
            atomicAdd(&g_t[(int)d23.x], p2);
            atomicAdd(&g_t[(int)d23.y], p3);
        } else {
            for (long long i = base; i < E; i++)
                atomicAdd(&g_t[(int)dst[i]], __ldg(&g_p[(int)src[i]]));
        }
    } else {
        const int* src = (const int*)edge;
        const int* dst = src + E;
        if (base + 3 < E) {
            int4 s = *reinterpret_cast<const int4*>(src + base);
            int4 d = *reinterpret_cast<const int4*>(dst + base);
            float p0 = __ldg(&g_p[s.x]);
            float p1 = __ldg(&g_p[s.y]);
            float p2 = __ldg(&g_p[s.z]);
            float p3 = __ldg(&g_p[s.w]);
            atomicAdd(&g_t[d.x], p0);
            atomicAdd(&g_t[d.y], p1);
            atomicAdd(&g_t[d.z], p2);
            atomicAdd(&g_t[d.w], p3);
        } else {
            for (long long i = base; i < E; i++)
                atomicAdd(&g_t[dst[i]], __ldg(&g_p[src[i]]));
        }
    }
}

// ---------------------------------------------------------------- node pass B: h, g, q
__global__ void k_nodeB(const float* __restrict__ x,
                        const float* __restrict__ W1,
                        const float* __restrict__ b1,
                        const float* __restrict__ W2, int n) {
    int i = blockIdx.x * blockDim.x + threadIdx.x;
    if (i >= n) return;
    float dis = g_deg[i];
    float xv  = x[i];
    float s   = dis * (g_t[i] + dis * xv);
    float q0 = 0.0f, q1 = 0.0f;
#pragma unroll
    for (int k = 0; k < 8; k++) {
        float h = fmaxf(fmaf(s, __ldg(&W1[k]), __ldg(&b1[k])), 0.0f);
        q0 = fmaf(h, __ldg(&W2[2 * k + 0]), q0);
        q1 = fmaf(h, __ldg(&W2[2 * k + 1]), q1);
    }
    g_q[i] = make_float2(dis * q0, dis * q1);
}

// ---------------------------------------------------------------- scatter 2 (float2 red)
__device__ __forceinline__ void red_add_v2(float2* addr, float a, float b) {
    asm volatile("red.global.add.v2.f32 [%0], {%1, %2};"
                 :: "l"(addr), "f"(a), "f"(b) : "memory");
}

__global__ void k_scatter2(const void* __restrict__ edge, int E) {
    long long base = (long long)(blockIdx.x * blockDim.x + threadIdx.x) * 4;
    if (g_is64) {
        const long long* src = (const long long*)edge;
        const long long* dst = src + E;
        if (base + 3 < E) {
            longlong2 s01 = *reinterpret_cast<const longlong2*>(src + base);
            longlong2 s23 = *reinterpret_cast<const longlong2*>(src + base + 2);
            longlong2 d01 = *reinterpret_cast<const longlong2*>(dst + base);
            longlong2 d23 = *reinterpret_cast<const longlong2*>(dst + base + 2);
            float2 q0 = __ldg(&g_q[(int)s01.x]);
            float2 q1 = __ldg(&g_q[(int)s01.y]);
            float2 q2 = __ldg(&g_q[(int)s23.x]);
            float2 q3 = __ldg(&g_q[(int)s23.y]);
            red_add_v2(&g_U[(int)d01.x], q0.x, q0.y);
            red_add_v2(&g_U[(int)d01.y], q1.x, q1.y);
            red_add_v2(&g_U[(int)d23.x], q2.x, q2.y);
            red_add_v2(&g_U[(int)d23.y], q3.x, q3.y);
        } else {
            for (long long i = base; i < E; i++) {
                float2 q = __ldg(&g_q[(int)src[i]]);
                red_add_v2(&g_U[(int)dst[i]], q.x, q.y);
            }
        }
    } else {
        const int* src = (const int*)edge;
        const int* dst = src + E;
        if (base + 3 < E) {
            int4 s = *reinterpret_cast<const int4*>(src + base);
            int4 d = *reinterpret_cast<const int4*>(dst + base);
            float2 q0 = __ldg(&g_q[s.x]);
            float2 q1 = __ldg(&g_q[s.y]);
            float2 q2 = __ldg(&g_q[s.z]);
            float2 q3 = __ldg(&g_q[s.w]);
            red_add_v2(&g_U[d.x], q0.x, q0.y);
            red_add_v2(&g_U[d.y], q1.x, q1.y);
            red_add_v2(&g_U[d.z], q2.x, q2.y);
            red_add_v2(&g_U[d.w], q3.x, q3.y);
        } else {
            for (long long i = base; i < E; i++) {
                float2 q = __ldg(&g_q[src[i]]);
                red_add_v2(&g_U[dst[i]], q.x, q.y);
            }
        }
    }
}

// ---------------------------------------------------------------- final
__global__ void k_final(const float* __restrict__ b2, float2* __restrict__ out, int n) {
    int i = blockIdx.x * blockDim.x + threadIdx.x;
    if (i >= n) return;
    float  dis = g_deg[i];
    float2 q   = g_q[i];
    float2 U   = g_U[i];
    float  b20 = __ldg(&b2[0]);
    float  b21 = __ldg(&b2[1]);
    out[i] = make_float2(fmaf(dis, U.x + q.x, b20),
                         fmaf(dis, U.y + q.y, b21));
}

// ================================================================ launch
extern "C" void kernel_launch(void* const* d_in, const int* in_sizes, int n_in,
                              void* d_out, int out_size) {
    const float* x  = (const float*)d_in[0];
    const void*  ei = d_in[1];            // [2, E]: src then dst; int32 or int64
    const float* W1 = (const float*)d_in[2];
    const float* b1 = (const float*)d_in[3];
    const float* W2 = (const float*)d_in[4];
    const float* b2 = (const float*)d_in[5];

    const int N = in_sizes[0];            // 500000
    const int E = in_sizes[1] / 2;        // 16000000

    const int NT = 256;
    const int nb_node = (N + NT - 1) / NT;
    const int nb_edge = (int)(((long long)E + 4 * NT - 1) / (4 * NT));

    k_detect  <<<1, 32>>>((const long long*)ei, 64, N);
    k_init    <<<nb_node, NT>>>(N);
    k_deg     <<<nb_edge, NT>>>(ei, E);
    k_nodeA   <<<nb_node, NT>>>(x, N);
    k_scatter1<<<nb_edge, NT>>>(ei, E);
    k_nodeB   <<<nb_node, NT>>>(x, W1, b1, W2, N);
    k_scatter2<<<nb_edge, NT>>>(ei, E);
    k_final   <<<nb_node, NT>>>(b2, (float2*)d_out, N);
}